// round 7
// baseline (speedup 1.0000x reference)
#include <cuda_runtime.h>
#include <cstddef>

#define Bc 32
#define Tc 4096
#define Dc 128
#define CHUNKS 64
#define ROWS (Tc / CHUNKS)   // 64 rows per block
#define NEG_FILL (-1e30f)
#define ALPHA 0.5f

// Scratch (fully overwritten every launch -> no init kernel needed, graph-safe)
__device__ float g_part[Bc * CHUNKS * 4 * Dc];  // [b][chunk][stat][d]; 4 MB
__device__ float g_sumsq[Bc * CHUNKS];
__device__ float g_bres1[Bc];
__device__ float g_bres2[Bc];

// lengths may arrive as int64 (declared) or int32 (JAX x64 disabled).
// Detect from the first 128 bytes: int32 payload read as int64 yields values
// outside [0, 2^31) unless all odd int32 slots are zero (prob ~ (1/4096)^16).
__device__ __forceinline__ long long read_len(const void* lp, int b) {
    const long long* p64 = (const long long*)lp;
    bool is64 = true;
#pragma unroll
    for (int i = 0; i < 16; i++) {          // 16 * 8B = 128B, safe for both layouts
        long long v = p64[i];
        if (v < 0 || v >= (1LL << 31)) is64 = false;
    }
    if (is64) return p64[b];
    return (long long)((const int*)lp)[b];
}

__device__ __forceinline__ float4 max4(float4 a, float4 b) {
    float4 r;
    r.x = fmaxf(a.x, b.x); r.y = fmaxf(a.y, b.y);
    r.z = fmaxf(a.z, b.z); r.w = fmaxf(a.w, b.w);
    return r;
}

// Streaming (evict-first) float4 load: data is single-use, 128 MB >> L2.
__device__ __forceinline__ float4 ldcs4(const float4* p) {
    float4 v;
    asm volatile("ld.global.cs.v4.f32 {%0,%1,%2,%3}, [%4];"
                 : "=f"(v.x), "=f"(v.y), "=f"(v.z), "=f"(v.w)
                 : "l"(p));
    return v;
}

__global__ __launch_bounds__(256) void seg_k1(
    const float4* __restrict__ O, const float4* __restrict__ Lb,
    const void* __restrict__ lens)
{
    const int b   = blockIdx.y;
    const int c   = blockIdx.x;
    const int tid = threadIdx.x;
    const int col4 = tid & 31;      // d-group (4 floats); D=128 -> 32 float4 per row
    const int rg   = tid >> 5;      // row group 0..7; whole warp shares one t -> uniform branches

    const long long len  = read_len(lens, b);
    const long long half = len >> 1;
    const int t0 = c * ROWS;

    const float4* Op = O  + ((size_t)b * Tc + t0) * 32 + col4;
    const float4* Lp = Lb + ((size_t)b * Tc + t0) * 32 + col4;

    float4 mOF = {NEG_FILL, NEG_FILL, NEG_FILL, NEG_FILL};
    float4 mLF = mOF, mOS = mOF, mLS = mOF;
    float sum = 0.0f;

    // 8 iterations, fully unrolled -> up to 16 independent loads front-batched
#pragma unroll
    for (int r = rg; r < ROWS; r += 8) {
        float4 o = ldcs4(Op + (size_t)r * 32);
        float4 l = ldcs4(Lp + (size_t)r * 32);
        float dx = o.x - l.x, dy = o.y - l.y, dz = o.z - l.z, dw = o.w - l.w;
        sum += dx * dx + dy * dy + dz * dz + dw * dw;
        long long t = (long long)(t0 + r);
        if (t < half) {                 // warp-uniform
            mOF = max4(mOF, o); mLF = max4(mLF, l);
        } else if (t < len) {
            mOS = max4(mOS, o); mLS = max4(mLS, l);
        }
    }

    __shared__ float4 sm[4 * 8 * 32];   // [stat][rg][col4] = 16 KB
    sm[(0 * 8 + rg) * 32 + col4] = mOF;
    sm[(1 * 8 + rg) * 32 + col4] = mLF;
    sm[(2 * 8 + rg) * 32 + col4] = mOS;
    sm[(3 * 8 + rg) * 32 + col4] = mLS;

    __shared__ float ss[256];
    ss[tid] = sum;
    __syncthreads();

    if (tid < 32) {
#pragma unroll
        for (int stat = 0; stat < 4; stat++) {
            float4 m = sm[(stat * 8 + 0) * 32 + tid];
#pragma unroll
            for (int r = 1; r < 8; r++)
                m = max4(m, sm[(stat * 8 + r) * 32 + tid]);
            ((float4*)g_part)[((b * CHUNKS + c) * 4 + stat) * 32 + tid] = m;
        }
    }

    for (int s = 128; s > 0; s >>= 1) {
        if (tid < s) ss[tid] += ss[tid + s];
        __syncthreads();
    }
    if (tid == 0) g_sumsq[b * CHUNKS + c] = ss[0];
}

// One block per b, 512 threads: 4 chunk-groups (16 chunks each) per d-value.
__global__ __launch_bounds__(512) void seg_k2(const void* __restrict__ lens)
{
    const int b  = blockIdx.x;
    const int d  = threadIdx.x & 127;   // 0..127
    const int cg = threadIdx.x >> 7;    // 0..3 chunk-group

    float m0 = NEG_FILL, m1 = NEG_FILL, m2 = NEG_FILL, m3 = NEG_FILL;
#pragma unroll
    for (int i = 0; i < CHUNKS / 4; i++) {
        int c = cg * (CHUNKS / 4) + i;
        const float* p = g_part + (size_t)((b * CHUNKS + c) * 4) * Dc;
        m0 = fmaxf(m0, p[0 * Dc + d]);
        m1 = fmaxf(m1, p[1 * Dc + d]);
        m2 = fmaxf(m2, p[2 * Dc + d]);
        m3 = fmaxf(m3, p[3 * Dc + d]);
    }

    __shared__ float sm[4][4][128];     // [stat][cg][d] = 8 KB
    sm[0][cg][d] = m0;
    sm[1][cg][d] = m1;
    sm[2][cg][d] = m2;
    sm[3][cg][d] = m3;
    __syncthreads();

    __shared__ float s1[128], s2[128];
    if (threadIdx.x < 128) {
        float mOF = fmaxf(fmaxf(sm[0][0][d], sm[0][1][d]), fmaxf(sm[0][2][d], sm[0][3][d]));
        float mLF = fmaxf(fmaxf(sm[1][0][d], sm[1][1][d]), fmaxf(sm[1][2][d], sm[1][3][d]));
        float mOS = fmaxf(fmaxf(sm[2][0][d], sm[2][1][d]), fmaxf(sm[2][2][d], sm[2][3][d]));
        float mLS = fmaxf(fmaxf(sm[3][0][d], sm[3][1][d]), fmaxf(sm[3][2][d], sm[3][3][d]));
        float d1 = mOF - mLF;   // empty segment: (-1e30)-(-1e30)=0, matches reference
        float d2 = mOS - mLS;
        s1[d] = d1 * d1;
        s2[d] = d2 * d2;
    }
    __syncthreads();
    for (int s = 64; s > 0; s >>= 1) {
        if (threadIdx.x < s) {
            s1[threadIdx.x] += s1[threadIdx.x + s];
            s2[threadIdx.x] += s2[threadIdx.x + s];
        }
        __syncthreads();
    }
    if (threadIdx.x == 0) {
        long long len = read_len(lens, b);
        float valid = (len >= 2) ? 1.0f : 0.0f;
        g_bres1[b] = valid * (s1[0] / (float)Dc);
        g_bres2[b] = valid * (s2[0] / (float)Dc);
    }
}

__global__ void seg_k3(float* __restrict__ out)
{
    const int lane = threadIdx.x;   // 32 threads
    double s = 0.0;                 // fp64: keep final accumulation far from the 1e-3 edge
    for (int i = lane; i < Bc * CHUNKS; i += 32) s += (double)g_sumsq[i];
    float r1 = g_bres1[lane];
    float r2 = g_bres2[lane];
#pragma unroll
    for (int o = 16; o > 0; o >>= 1) {
        s  += __shfl_down_sync(0xFFFFFFFFu, s,  o);
        r1 += __shfl_down_sync(0xFFFFFFFFu, r1, o);
        r2 += __shfl_down_sync(0xFFFFFFFFu, r2, o);
    }
    if (lane == 0) {
        double base = s / (double)((size_t)Bc * Tc * Dc);
        out[0] = (float)(base + (double)ALPHA * (((double)r1 + (double)r2) / (double)Bc));
    }
}

extern "C" void kernel_launch(void* const* d_in, const int* in_sizes, int n_in,
                              void* d_out, int out_size)
{
    const float4* outputs = (const float4*)d_in[0];
    const float4* labels  = (const float4*)d_in[1];
    const void*   lens    = d_in[2];
    float* out = (float*)d_out;

    dim3 g1(CHUNKS, Bc);
    seg_k1<<<g1, 256>>>(outputs, labels, lens);
    seg_k2<<<Bc, 512>>>(lens);
    seg_k3<<<1, 32>>>(out);
}

// round 9
// speedup vs baseline: 1.2956x; 1.2956x over previous
#include <cuda_runtime.h>
#include <cstdint>
#include <cstddef>

#define Bc 32
#define Tc 4096
#define Dc 128
#define CHUNKS 16
#define ROWS (Tc / CHUNKS)      // 256 rows per block
#define SROWS 16                // rows per pipeline stage
#define NST (ROWS / SROWS)      // 16 stages
#define STAGE_BYTES (SROWS * Dc * 4)   // 8192 B per tensor per stage
#define NEG_FILL (-1e30f)
#define ALPHA 0.5f

// Scratch: fully overwritten every launch (graph-safe, allocation-free).
__device__ float g_part[Bc * CHUNKS * 4 * Dc];  // [b][chunk][stat][d]; 1 MB
__device__ float g_csum[Bc * CHUNKS];
__device__ float g_bsum[Bc];
__device__ float g_bres1[Bc];
__device__ float g_bres2[Bc];
__device__ unsigned g_count;    // zero-init; reset to 0 by finalizer each launch

// lengths may arrive as int64 (declared) or int32 (JAX x64 disabled).
// int32 payload read as int64 yields values outside [0, 2^31) w.p. ~1.
__device__ __forceinline__ long long read_len(const void* lp, int b) {
    const long long* p64 = (const long long*)lp;
    bool is64 = true;
#pragma unroll
    for (int i = 0; i < 16; i++) {          // first 128B, safe for both layouts
        long long v = p64[i];
        if (v < 0 || v >= (1LL << 31)) is64 = false;
    }
    if (is64) return p64[b];
    return (long long)((const int*)lp)[b];
}

__device__ __forceinline__ float4 max4(float4 a, float4 b) {
    float4 r;
    r.x = fmaxf(a.x, b.x); r.y = fmaxf(a.y, b.y);
    r.z = fmaxf(a.z, b.z); r.w = fmaxf(a.w, b.w);
    return r;
}

// ---- mbarrier / bulk-copy helpers --------------------------------------
__device__ __forceinline__ uint32_t s2u(const void* p) {
    return (uint32_t)__cvta_generic_to_shared(p);
}
__device__ __forceinline__ void mbar_init(uint32_t a, unsigned cnt) {
    asm volatile("mbarrier.init.shared::cta.b64 [%0], %1;" :: "r"(a), "r"(cnt) : "memory");
}
__device__ __forceinline__ void mbar_expect(uint32_t a, uint32_t tx) {
    asm volatile("mbarrier.arrive.expect_tx.shared::cta.b64 _, [%0], %1;"
                 :: "r"(a), "r"(tx) : "memory");
}
__device__ __forceinline__ void bulk_g2s(uint32_t dst, const void* src,
                                         uint32_t bytes, uint32_t bar) {
    asm volatile("cp.async.bulk.shared::cta.global.mbarrier::complete_tx::bytes "
                 "[%0], [%1], %2, [%3];"
                 :: "r"(dst), "l"(src), "r"(bytes), "r"(bar) : "memory");
}
__device__ __forceinline__ void mbar_wait(uint32_t a, uint32_t parity) {
    asm volatile(
        "{\n\t.reg .pred P;\n"
        "W_%=:\n\t"
        "mbarrier.try_wait.parity.acquire.cta.shared::cta.b64 P, [%0], %1, 0x989680;\n\t"
        "@P bra D_%=;\n\t"
        "bra W_%=;\n"
        "D_%=:\n\t}"
        :: "r"(a), "r"(parity) : "memory");
}
// ------------------------------------------------------------------------

__global__ __launch_bounds__(256) void seg_k1(
    const float* __restrict__ O, const float* __restrict__ Lb,
    const void* __restrict__ lens)
{
    __shared__ __align__(16) float bufO[2][SROWS * Dc];   // 16 KB
    __shared__ __align__(16) float bufL[2][SROWS * Dc];   // 16 KB
    __shared__ __align__(8) unsigned long long bar_s[2];

    const int b   = blockIdx.y;
    const int c   = blockIdx.x;
    const int tid = threadIdx.x;
    const int col4 = tid & 31;   // d-group of 4 floats
    const int rg   = tid >> 5;   // 0..7; whole warp shares one row -> uniform masks

    const long long len  = read_len(lens, b);
    const long long half = len >> 1;
    const int t0 = c * ROWS;

    const char* gO = (const char*)(O  + ((size_t)b * Tc + t0) * Dc);
    const char* gL = (const char*)(Lb + ((size_t)b * Tc + t0) * Dc);

    const uint32_t bar0 = s2u(&bar_s[0]);
    const uint32_t bar1 = s2u(&bar_s[1]);
    const uint32_t dO0 = s2u(&bufO[0][0]), dO1 = s2u(&bufO[1][0]);
    const uint32_t dL0 = s2u(&bufL[0][0]), dL1 = s2u(&bufL[1][0]);

    if (tid == 0) { mbar_init(bar0, 1); mbar_init(bar1, 1); }
    __syncthreads();

    // Prologue: prefetch stages 0 and 1 (depth-2 pipeline)
    if (tid == 0) {
        mbar_expect(bar0, 2 * STAGE_BYTES);
        bulk_g2s(dO0, gO, STAGE_BYTES, bar0);
        bulk_g2s(dL0, gL, STAGE_BYTES, bar0);
        mbar_expect(bar1, 2 * STAGE_BYTES);
        bulk_g2s(dO1, gO + STAGE_BYTES, STAGE_BYTES, bar1);
        bulk_g2s(dL1, gL + STAGE_BYTES, STAGE_BYTES, bar1);
    }

    float4 mOF = {NEG_FILL, NEG_FILL, NEG_FILL, NEG_FILL};
    float4 mLF = mOF, mOS = mOF, mLS = mOF;
    float sum = 0.0f;

#pragma unroll 1
    for (int s = 0; s < NST; s++) {
        const int buf = s & 1;
        mbar_wait(buf ? bar1 : bar0, (s >> 1) & 1);

        const float4* pO = (const float4*)bufO[buf];
        const float4* pL = (const float4*)bufL[buf];
#pragma unroll
        for (int rr = 0; rr < 2; rr++) {
            const int r = rg + rr * 8;            // 0..15 within stage
            float4 o = pO[r * 32 + col4];
            float4 l = pL[r * 32 + col4];
            float dx = o.x - l.x, dy = o.y - l.y, dz = o.z - l.z, dw = o.w - l.w;
            sum += dx * dx + dy * dy + dz * dz + dw * dw;
            long long t = (long long)(t0 + s * SROWS + r);
            if (t < half) {                        // warp-uniform
                mOF = max4(mOF, o); mLF = max4(mLF, l);
            } else if (t < len) {
                mOS = max4(mOS, o); mLS = max4(mLS, l);
            }
        }
        __syncthreads();                           // all consumers done with buf

        if (s + 2 < NST && tid == 0) {
            const size_t off = (size_t)(s + 2) * STAGE_BYTES;
            mbar_expect(buf ? bar1 : bar0, 2 * STAGE_BYTES);
            bulk_g2s(buf ? dO1 : dO0, gO + off, STAGE_BYTES, buf ? bar1 : bar0);
            bulk_g2s(buf ? dL1 : dL0, gL + off, STAGE_BYTES, buf ? bar1 : bar0);
        }
    }

    // Reuse stage buffers as reduction scratch (all reads complete: synced above).
    float4* red = (float4*)bufO;        // 4 stats * 8 rg * 32 col4 = 16 KB
    float*  ss  = (float*)bufL;         // 256 floats
    red[(0 * 8 + rg) * 32 + col4] = mOF;
    red[(1 * 8 + rg) * 32 + col4] = mLF;
    red[(2 * 8 + rg) * 32 + col4] = mOS;
    red[(3 * 8 + rg) * 32 + col4] = mLS;
    ss[tid] = sum;
    __syncthreads();

    if (tid < 32) {
#pragma unroll
        for (int stat = 0; stat < 4; stat++) {
            float4 m = red[(stat * 8 + 0) * 32 + tid];
#pragma unroll
            for (int r = 1; r < 8; r++)
                m = max4(m, red[(stat * 8 + r) * 32 + tid]);
            ((float4*)g_part)[((b * CHUNKS + c) * 4 + stat) * 32 + tid] = m;
        }
    }
    for (int s = 128; s > 0; s >>= 1) {
        if (tid < s) ss[tid] += ss[tid + s];
        __syncthreads();
    }
    if (tid == 0) g_csum[b * CHUNKS + c] = ss[0];
}

// One block per b (128 threads). Last-finished block does the final scalar.
__global__ __launch_bounds__(128) void seg_k2(const void* __restrict__ lens,
                                              float* __restrict__ out)
{
    const int b = blockIdx.x;
    const int d = threadIdx.x;   // 0..127

    float mOF = NEG_FILL, mLF = NEG_FILL, mOS = NEG_FILL, mLS = NEG_FILL;
#pragma unroll
    for (int c = 0; c < CHUNKS; c++) {
        const float* p = g_part + (size_t)((b * CHUNKS + c) * 4) * Dc;
        mOF = fmaxf(mOF, p[0 * Dc + d]);
        mLF = fmaxf(mLF, p[1 * Dc + d]);
        mOS = fmaxf(mOS, p[2 * Dc + d]);
        mLS = fmaxf(mLS, p[3 * Dc + d]);
    }
    float d1 = mOF - mLF;   // empty segment: (-1e30)-(-1e30)=0, matches reference
    float d2 = mOS - mLS;

    __shared__ float s1[128], s2[128], sc[128];
    s1[d] = d1 * d1;
    s2[d] = d2 * d2;
    sc[d] = (d < CHUNKS) ? g_csum[b * CHUNKS + d] : 0.0f;
    __syncthreads();
    for (int s = 64; s > 0; s >>= 1) {
        if (d < s) { s1[d] += s1[d + s]; s2[d] += s2[d + s]; sc[d] += sc[d + s]; }
        __syncthreads();
    }

    if (d == 0) {
        long long len = read_len(lens, b);
        float valid = (len >= 2) ? 1.0f : 0.0f;
        g_bres1[b] = valid * (s1[0] / (float)Dc);
        g_bres2[b] = valid * (s2[0] / (float)Dc);
        g_bsum[b]  = sc[0];
        __threadfence();
        unsigned old = atomicAdd(&g_count, 1u);
        if (old == Bc - 1) {                 // last block: finalize + reset counter
            __threadfence();
            g_count = 0;
            double s = 0.0;
            float r1 = 0.0f, r2 = 0.0f;
#pragma unroll
            for (int i = 0; i < Bc; i++) {
                s  += (double)g_bsum[i];
                r1 += g_bres1[i];
                r2 += g_bres2[i];
            }
            double base = s / (double)((size_t)Bc * Tc * Dc);
            out[0] = (float)(base + (double)ALPHA *
                             (((double)r1 + (double)r2) / (double)Bc));
        }
    }
}

extern "C" void kernel_launch(void* const* d_in, const int* in_sizes, int n_in,
                              void* d_out, int out_size)
{
    const float* outputs = (const float*)d_in[0];
    const float* labels  = (const float*)d_in[1];
    const void*  lens    = d_in[2];
    float* out = (float*)d_out;

    dim3 g1(CHUNKS, Bc);
    seg_k1<<<g1, 256>>>(outputs, labels, lens);
    seg_k2<<<Bc, 128>>>(lens, out);
}

// round 10
// speedup vs baseline: 1.3720x; 1.0589x over previous
#include <cuda_runtime.h>
#include <cstdint>
#include <cstddef>

#define Bc 32
#define Tc 4096
#define Dc 128
#define CHUNKS 16
#define ROWS (Tc / CHUNKS)      // 256 rows per block
#define SROWS 16                // rows per pipeline stage
#define NST (ROWS / SROWS)      // 16 stages
#define STAGE_BYTES (SROWS * Dc * 4)   // 8192 B per tensor per stage
#define NEG_FILL (-1e30f)
#define ALPHA 0.5f

// Scratch: fully overwritten (or counter-reset) every launch -> graph-safe.
__device__ float g_part[Bc * CHUNKS * 4 * Dc];  // [b][chunk][stat][d]; 1 MB
__device__ float g_csum[Bc * CHUNKS];
__device__ float g_bsum[Bc];
__device__ float g_bres1[Bc];
__device__ float g_bres2[Bc];
__device__ unsigned g_bcount[Bc];   // zero-init; reset by per-b electee
__device__ unsigned g_count;        // zero-init; reset by global electee

// lengths may arrive as int64 (declared) or int32 (JAX x64 disabled).
// int32 payload read as int64 yields values outside [0, 2^31) w.p. ~1.
__device__ __forceinline__ long long read_len(const void* lp, int b) {
    const long long* p64 = (const long long*)lp;
    bool is64 = true;
#pragma unroll
    for (int i = 0; i < 16; i++) {          // first 128B, safe for both layouts
        long long v = p64[i];
        if (v < 0 || v >= (1LL << 31)) is64 = false;
    }
    if (is64) return p64[b];
    return (long long)((const int*)lp)[b];
}

__device__ __forceinline__ float4 max4(float4 a, float4 b) {
    float4 r;
    r.x = fmaxf(a.x, b.x); r.y = fmaxf(a.y, b.y);
    r.z = fmaxf(a.z, b.z); r.w = fmaxf(a.w, b.w);
    return r;
}

// ---- mbarrier / bulk-copy helpers --------------------------------------
__device__ __forceinline__ uint32_t s2u(const void* p) {
    return (uint32_t)__cvta_generic_to_shared(p);
}
__device__ __forceinline__ void mbar_init(uint32_t a, unsigned cnt) {
    asm volatile("mbarrier.init.shared::cta.b64 [%0], %1;" :: "r"(a), "r"(cnt) : "memory");
}
__device__ __forceinline__ void mbar_expect(uint32_t a, uint32_t tx) {
    asm volatile("mbarrier.arrive.expect_tx.shared::cta.b64 _, [%0], %1;"
                 :: "r"(a), "r"(tx) : "memory");
}
__device__ __forceinline__ void bulk_g2s(uint32_t dst, const void* src,
                                         uint32_t bytes, uint32_t bar) {
    asm volatile("cp.async.bulk.shared::cta.global.mbarrier::complete_tx::bytes "
                 "[%0], [%1], %2, [%3];"
                 :: "r"(dst), "l"(src), "r"(bytes), "r"(bar) : "memory");
}
__device__ __forceinline__ void mbar_wait(uint32_t a, uint32_t parity) {
    asm volatile(
        "{\n\t.reg .pred P;\n"
        "W_%=:\n\t"
        "mbarrier.try_wait.parity.acquire.cta.shared::cta.b64 P, [%0], %1, 0x989680;\n\t"
        "@P bra D_%=;\n\t"
        "bra W_%=;\n"
        "D_%=:\n\t}"
        :: "r"(a), "r"(parity) : "memory");
}
// ------------------------------------------------------------------------

__global__ __launch_bounds__(256) void seg_k1(
    const float* __restrict__ O, const float* __restrict__ Lb,
    const void* __restrict__ lens, float* __restrict__ out)
{
    __shared__ __align__(16) float bufO[2][SROWS * Dc];   // 16 KB
    __shared__ __align__(16) float bufL[2][SROWS * Dc];   // 16 KB
    __shared__ __align__(8) unsigned long long bar_s[2];
    __shared__ int s_elected, s_final;

    const int b   = blockIdx.y;
    const int c   = blockIdx.x;
    const int tid = threadIdx.x;
    const int col4 = tid & 31;   // d-group of 4 floats
    const int rg   = tid >> 5;   // 0..7; whole warp shares one row -> uniform masks

    const long long len  = read_len(lens, b);
    const long long half = len >> 1;
    const int t0 = c * ROWS;

    const char* gO = (const char*)(O  + ((size_t)b * Tc + t0) * Dc);
    const char* gL = (const char*)(Lb + ((size_t)b * Tc + t0) * Dc);

    const uint32_t bar0 = s2u(&bar_s[0]);
    const uint32_t bar1 = s2u(&bar_s[1]);
    const uint32_t dO0 = s2u(&bufO[0][0]), dO1 = s2u(&bufO[1][0]);
    const uint32_t dL0 = s2u(&bufL[0][0]), dL1 = s2u(&bufL[1][0]);

    if (tid == 0) { mbar_init(bar0, 1); mbar_init(bar1, 1); }
    __syncthreads();

    // Prologue: prefetch stages 0 and 1 (depth-2 pipeline)
    if (tid == 0) {
        mbar_expect(bar0, 2 * STAGE_BYTES);
        bulk_g2s(dO0, gO, STAGE_BYTES, bar0);
        bulk_g2s(dL0, gL, STAGE_BYTES, bar0);
        mbar_expect(bar1, 2 * STAGE_BYTES);
        bulk_g2s(dO1, gO + STAGE_BYTES, STAGE_BYTES, bar1);
        bulk_g2s(dL1, gL + STAGE_BYTES, STAGE_BYTES, bar1);
    }

    float4 mOF = {NEG_FILL, NEG_FILL, NEG_FILL, NEG_FILL};
    float4 mLF = mOF, mOS = mOF, mLS = mOF;
    float sum = 0.0f;

#pragma unroll 1
    for (int s = 0; s < NST; s++) {
        const int buf = s & 1;
        mbar_wait(buf ? bar1 : bar0, (s >> 1) & 1);

        const float4* pO = (const float4*)bufO[buf];
        const float4* pL = (const float4*)bufL[buf];
#pragma unroll
        for (int rr = 0; rr < 2; rr++) {
            const int r = rg + rr * 8;            // 0..15 within stage
            float4 o = pO[r * 32 + col4];
            float4 l = pL[r * 32 + col4];
            float dx = o.x - l.x, dy = o.y - l.y, dz = o.z - l.z, dw = o.w - l.w;
            sum += dx * dx + dy * dy + dz * dz + dw * dw;
            long long t = (long long)(t0 + s * SROWS + r);
            if (t < half) {                        // warp-uniform
                mOF = max4(mOF, o); mLF = max4(mLF, l);
            } else if (t < len) {
                mOS = max4(mOS, o); mLS = max4(mLS, l);
            }
        }
        __syncthreads();                           // all consumers done with buf

        if (s + 2 < NST && tid == 0) {
            const size_t off = (size_t)(s + 2) * STAGE_BYTES;
            mbar_expect(buf ? bar1 : bar0, 2 * STAGE_BYTES);
            bulk_g2s(buf ? dO1 : dO0, gO + off, STAGE_BYTES, buf ? bar1 : bar0);
            bulk_g2s(buf ? dL1 : dL0, gL + off, STAGE_BYTES, buf ? bar1 : bar0);
        }
    }

    // ---- intra-block reduction (reuse stage buffers as scratch) ----
    float4* red = (float4*)bufO;        // 4 stats * 8 rg * 32 col4 = 16 KB
    float*  ss  = (float*)bufL;         // [0..255]
    red[(0 * 8 + rg) * 32 + col4] = mOF;
    red[(1 * 8 + rg) * 32 + col4] = mLF;
    red[(2 * 8 + rg) * 32 + col4] = mOS;
    red[(3 * 8 + rg) * 32 + col4] = mLS;
    ss[tid] = sum;
    __syncthreads();

    if (tid < 32) {
#pragma unroll
        for (int stat = 0; stat < 4; stat++) {
            float4 m = red[(stat * 8 + 0) * 32 + tid];
#pragma unroll
            for (int r = 1; r < 8; r++)
                m = max4(m, red[(stat * 8 + r) * 32 + tid]);
            ((float4*)g_part)[((b * CHUNKS + c) * 4 + stat) * 32 + tid] = m;
        }
    }
    for (int s = 128; s > 0; s >>= 1) {
        if (tid < s) ss[tid] += ss[tid + s];
        __syncthreads();
    }
    if (tid == 0) g_csum[b * CHUNKS + c] = ss[0];

    // Publish this chunk's partials, then elect the last chunk-block of b.
    if (tid < 32) __threadfence();      // tid0 fence also covers its g_csum store
    if (tid == 0) {
        unsigned old = atomicAdd(&g_bcount[b], 1u);
        s_elected = (old == CHUNKS - 1) ? 1 : 0;
    }
    __syncthreads();
    if (!s_elected) return;

    // ---- per-b reduction over 16 chunks (L2-hot, 32 KB) ----
    __threadfence();                    // acquire side
    float* s1 = ((float*)bufL) + 256;   // [256..383]
    float* s2 = ((float*)bufL) + 384;   // [384..511]
    if (tid < 128) {
        const int d = tid;
        float r0 = NEG_FILL, r1 = NEG_FILL, r2 = NEG_FILL, r3 = NEG_FILL;
#pragma unroll
        for (int cc = 0; cc < CHUNKS; cc++) {
            const float* p = g_part + (size_t)((b * CHUNKS + cc) * 4) * Dc;
            r0 = fmaxf(r0, p[0 * Dc + d]);
            r1 = fmaxf(r1, p[1 * Dc + d]);
            r2 = fmaxf(r2, p[2 * Dc + d]);
            r3 = fmaxf(r3, p[3 * Dc + d]);
        }
        float d1 = r0 - r1;   // empty segment: (-1e30)-(-1e30)=0, matches reference
        float d2 = r2 - r3;
        s1[d] = d1 * d1;
        s2[d] = d2 * d2;
    }
    ss[tid] = (tid < CHUNKS) ? g_csum[b * CHUNKS + tid] : 0.0f;
    __syncthreads();
    for (int s = 64; s > 0; s >>= 1) {
        if (tid < s) {
            s1[tid] += s1[tid + s];
            s2[tid] += s2[tid + s];
            ss[tid] += ss[tid + s];
        }
        __syncthreads();
    }

    if (tid == 0) {
        float valid = (len >= 2) ? 1.0f : 0.0f;
        g_bres1[b] = valid * (s1[0] / (float)Dc);
        g_bres2[b] = valid * (s2[0] / (float)Dc);
        g_bsum[b]  = ss[0] + ss[64];    // loop left halves summed into [0]; [64] absorbed
        // NOTE: loop above fully reduces into ss[0]; the extra term is 0-safe only
        // if CHUNKS<=64. CHUNKS=16 -> ss[64]=0 contribution from init. Keep exact:
        g_bsum[b]  = ss[0];
        g_bcount[b] = 0;                // reset for next graph replay
        __threadfence();
        unsigned old = atomicAdd(&g_count, 1u);
        s_final = (old == Bc - 1) ? 1 : 0;
    }
    __syncthreads();
    if (!s_final) return;

    // ---- global finalizer: warp 0 reduces 32 per-b results ----
    __threadfence();
    if (tid < 32) {
        double s = (double)g_bsum[tid];
        float r1 = g_bres1[tid];
        float r2 = g_bres2[tid];
#pragma unroll
        for (int o = 16; o > 0; o >>= 1) {
            s  += __shfl_down_sync(0xFFFFFFFFu, s,  o);
            r1 += __shfl_down_sync(0xFFFFFFFFu, r1, o);
            r2 += __shfl_down_sync(0xFFFFFFFFu, r2, o);
        }
        if (tid == 0) {
            g_count = 0;                // reset for next graph replay
            double base = s / (double)((size_t)Bc * Tc * Dc);
            out[0] = (float)(base + (double)ALPHA *
                             (((double)r1 + (double)r2) / (double)Bc));
        }
    }
}

extern "C" void kernel_launch(void* const* d_in, const int* in_sizes, int n_in,
                              void* d_out, int out_size)
{
    const float* outputs = (const float*)d_in[0];
    const float* labels  = (const float*)d_in[1];
    const void*  lens    = d_in[2];
    float* out = (float*)d_out;

    dim3 g1(CHUNKS, Bc);
    seg_k1<<<g1, 256>>>(outputs, labels, lens, out);
}